// round 2
// baseline (speedup 1.0000x reference)
#include <cuda_runtime.h>

#define NTOK 50
#define DDIM 64
#define FP   68   // pitch for sF, sH (mult of 4 for float4 rows; banks (4n+d) for column reads)
#define QP   65   // pitch for sQ (scalar column reads, <=2-way conflicts)

// smem layout (floats):
//   sF [50][68]  = 3400
//   sK [64][64]  = 4096   (K_w row-major as-is)
//   sQ [64][65]  = 4160   (Q_w row-major, padded)
//   sG [64][64]  = 4096   (G = F^T F)
//   sH [50][68]  = 3400   (H = F @ K_w)
#define SMEM_FLOATS (NTOK*FP + 64*64 + 64*QP + 64*64 + NTOK*FP)

__global__ __launch_bounds__(256, 2)
void SAM3E_kernel(const float* __restrict__ Fg,
                  const float* __restrict__ Kw,
                  const float* __restrict__ Qw,
                  float* __restrict__ outg)
{
    extern __shared__ float sm[];
    float* sF = sm;
    float* sK = sF + NTOK * FP;
    float* sQ = sK + 64 * 64;
    float* sG = sQ + 64 * QP;
    float* sH = sG + 64 * 64;

    const int b   = blockIdx.x;
    const int tid = threadIdx.x;
    const float* Fb = Fg + (size_t)b * (NTOK * DDIM);

    // ---- stage inputs into smem (coalesced reads, conflict-free writes) ----
    for (int idx = tid; idx < NTOK * DDIM; idx += 256) {
        int n = idx >> 6, d = idx & 63;
        sF[n * FP + d] = Fb[idx];
    }
    for (int idx = tid; idx < 64 * 64; idx += 256) {
        sK[idx] = Kw[idx];                       // sK[d][e] = K_w[d][e]
    }
    for (int idx = tid; idx < 64 * 64; idx += 256) {
        int e = idx >> 6, d = idx & 63;
        sQ[e * QP + d] = Qw[idx];                // sQ[e][d] = Q_w[e][d]
    }
    __syncthreads();

    // ---- Phase 1: G = F^T F.  256 threads as 16x16, each a 4x4 tile ----
    {
        const int i = tid >> 4, j = tid & 15;
        float acc[4][4] = {};
        const float* fa = sF + 4 * i;
        const float* fb = sF + 4 * j;
        #pragma unroll 5
        for (int n = 0; n < NTOK; ++n) {
            float4 a4 = *(const float4*)(fa + n * FP);
            float4 b4 = *(const float4*)(fb + n * FP);
            float av[4] = {a4.x, a4.y, a4.z, a4.w};
            float bv[4] = {b4.x, b4.y, b4.z, b4.w};
            #pragma unroll
            for (int p = 0; p < 4; ++p)
                #pragma unroll
                for (int q = 0; q < 4; ++q)
                    acc[p][q] += av[p] * bv[q];
        }
        #pragma unroll
        for (int p = 0; p < 4; ++p)
            *(float4*)(sG + (4 * i + p) * 64 + 4 * j) =
                make_float4(acc[p][0], acc[p][1], acc[p][2], acc[p][3]);
    }
    // NOTE: phase 2 reads only sF/sK/sQ (synced above) and writes sH;
    // phase 1 writes sG. No hazard between them -> no extra sync here.

    // ---- Phase 2: H = F@K_w (to smem) and QF = F@Q_w^T (to regs) ----
    // 208 active threads: r = tid/16 in [0,13), c = tid%16. Tile rows 4r..4r+3, cols 4c..4c+3.
    const bool act = tid < 208;
    const int r  = tid >> 4;
    const int c  = tid & 15;
    const int n0 = 4 * r;
    const int e0 = 4 * c;

    int nr[4];
    #pragma unroll
    for (int a = 0; a < 4; ++a) {
        int n = n0 + a;
        nr[a] = (n < NTOK) ? n : (NTOK - 1);   // clamp loads; stores guarded
    }

    float qf[4][4] = {};
    if (act) {
        float h[4][4] = {};
        #pragma unroll 4
        for (int d = 0; d < 64; ++d) {
            float fv[4];
            #pragma unroll
            for (int a = 0; a < 4; ++a) fv[a] = sF[nr[a] * FP + d];
            float4 k4 = *(const float4*)(sK + d * 64 + e0);
            float kv[4] = {k4.x, k4.y, k4.z, k4.w};
            float qv[4];
            #pragma unroll
            for (int k = 0; k < 4; ++k) qv[k] = sQ[(e0 + k) * QP + d];
            #pragma unroll
            for (int a = 0; a < 4; ++a)
                #pragma unroll
                for (int k = 0; k < 4; ++k) {
                    h[a][k]  += fv[a] * kv[k];
                    qf[a][k] += fv[a] * qv[k];
                }
        }
        #pragma unroll
        for (int a = 0; a < 4; ++a)
            if (n0 + a < NTOK)
                *(float4*)(sH + (n0 + a) * FP + e0) =
                    make_float4(h[a][0], h[a][1], h[a][2], h[a][3]);
    }
    __syncthreads();   // sG (phase1) and sH (phase2) now visible

    // ---- Phase 3: T = H @ G, then out = F .* T + QF ----
    if (act) {
        float t[4][4] = {};
        #pragma unroll 4
        for (int e = 0; e < 64; ++e) {
            float hv[4];
            #pragma unroll
            for (int a = 0; a < 4; ++a) hv[a] = sH[nr[a] * FP + e];
            float4 g4 = *(const float4*)(sG + e * 64 + e0);
            float gv[4] = {g4.x, g4.y, g4.z, g4.w};
            #pragma unroll
            for (int a = 0; a < 4; ++a)
                #pragma unroll
                for (int k = 0; k < 4; ++k)
                    t[a][k] += hv[a] * gv[k];
        }
        float* ob = outg + (size_t)b * (NTOK * DDIM);
        #pragma unroll
        for (int a = 0; a < 4; ++a) {
            int n = n0 + a;
            if (n < NTOK) {
                float4 f4 = *(const float4*)(sF + n * FP + e0);
                float4 o;
                o.x = f4.x * t[a][0] + qf[a][0];
                o.y = f4.y * t[a][1] + qf[a][1];
                o.z = f4.z * t[a][2] + qf[a][2];
                o.w = f4.w * t[a][3] + qf[a][3];
                *(float4*)(ob + n * 64 + e0) = o;
            }
        }
    }
}

extern "C" void kernel_launch(void* const* d_in, const int* in_sizes, int n_in,
                              void* d_out, int out_size)
{
    const float* F  = (const float*)d_in[0];
    const float* Kw = (const float*)d_in[1];
    const float* Qw = (const float*)d_in[2];
    float* out      = (float*)d_out;

    const int B = in_sizes[0] / (NTOK * DDIM);   // 8192
    const int smem_bytes = SMEM_FLOATS * sizeof(float);  // 76,608 B

    cudaFuncSetAttribute(SAM3E_kernel,
                         cudaFuncAttributeMaxDynamicSharedMemorySize, smem_bytes);

    SAM3E_kernel<<<B, 256, smem_bytes>>>(F, Kw, Qw, out);
}

// round 5
// speedup vs baseline: 1.1616x; 1.1616x over previous
#include <cuda_runtime.h>

#define NTOK 50
#define BTOK 3200      // 50*64
#define PF 72          // sF pitch: type1 frag reads conflict-free
#define PK 72          // sK pitch: K_w stored row-major [d][e]; type1 reads conflict-free
#define PQ 68          // sQ pitch: type2 reads (row varies with g) conflict-free
#define PG 72          // sG pitch: type1 B reads conflict-free
#define PH 68          // sH pitch: type2 A reads conflict-free

#define SMEM_FLOATS (64*PF + 64*PK + 64*PQ + 64*PG + 64*PH)

__device__ __forceinline__ unsigned tf32_rna(float x) {
    unsigned u; asm("cvt.rna.tf32.f32 %0, %1;" : "=r"(u) : "f"(x)); return u;
}

__device__ __forceinline__ void mma8(float* d, const unsigned* a, const unsigned* b) {
    asm volatile(
        "mma.sync.aligned.m16n8k8.row.col.f32.tf32.tf32.f32 "
        "{%0,%1,%2,%3}, {%4,%5,%6,%7}, {%8,%9}, {%0,%1,%2,%3};\n"
        : "+f"(d[0]), "+f"(d[1]), "+f"(d[2]), "+f"(d[3])
        : "r"(a[0]), "r"(a[1]), "r"(a[2]), "r"(a[3]), "r"(b[0]), "r"(b[1]));
}

// split fragments into tf32 hi/lo
__device__ __forceinline__ void split4(const float* f, unsigned* h, unsigned* l) {
    #pragma unroll
    for (int i = 0; i < 4; ++i) {
        h[i] = tf32_rna(f[i]);
        l[i] = tf32_rna(f[i] - __uint_as_float(h[i]));
    }
}
__device__ __forceinline__ void split2(const float* f, unsigned* h, unsigned* l) {
    #pragma unroll
    for (int i = 0; i < 2; ++i) {
        h[i] = tf32_rna(f[i]);
        l[i] = tf32_rna(f[i] - __uint_as_float(h[i]));
    }
}

// acc += A*B with 3xTF32 split (drops lo*lo term; ~2^-22 rel err)
__device__ __forceinline__ void mma_split(float* acc, const unsigned* ah, const unsigned* al,
                                          const unsigned* bh, const unsigned* bl) {
    mma8(acc, ah, bh);
    mma8(acc, al, bh);
    mma8(acc, ah, bl);
}

__global__ __launch_bounds__(256, 2)
void SAM3E_kernel(const float* __restrict__ Fg,
                  const float* __restrict__ Kw,
                  const float* __restrict__ Qw,
                  float* __restrict__ outg)
{
    extern __shared__ float sm[];
    float* sF = sm;                    // [64][PF] rows 50..63 zeroed
    float* sK = sF + 64 * PF;          // K_w row-major [d][e], pitch PK  (NO transpose!)
    float* sQ = sK + 64 * PK;          // Q_w row-major [e][d], pitch PQ  (transpose via read)
    float* sG = sQ + 64 * PQ;          // G = F^T F, pitch PG
    float* sH = sG + 64 * PG;          // H = F @ K_w, pitch PH

    const int b   = blockIdx.x;
    const int tid = threadIdx.x;
    const float* Fb = Fg + (size_t)b * BTOK;

    // ---- stage ----
    for (int idx = tid; idx < BTOK; idx += 256) {       // F rows 0..49
        int n = idx >> 6, d = idx & 63;
        sF[n * PF + d] = Fb[idx];
    }
    for (int idx = tid; idx < 14 * PF; idx += 256)      // zero pad rows 50..63
        sF[50 * PF + idx] = 0.0f;
    for (int idx = tid; idx < 4096; idx += 256) {
        int r = idx >> 6, c = idx & 63;
        sK[r * PK + c] = Kw[idx];                        // sK[d][e] = K_w[d][e]
        sQ[r * PQ + c] = Qw[idx];                        // sQ[e][d] = Q_w[e][d]
    }
    __syncthreads();

    const int w    = tid >> 5;
    const int lane = tid & 31;
    const int g    = lane >> 2;        // 0..7
    const int t4   = lane & 3;         // 0..3
    const int m0   = (w >> 1) * 16;    // m-band rows m0..m0+15
    const int n0   = (w & 1) * 32;     // n-half cols n0..n0+31 (4 n8-tiles)

    float accG[4][4] = {};
    float accH[4][4] = {};
    float accQ[4][4] = {};

    // ---- Phase A1: G = F^T F   (M=64(d), N=64(d'), K=56(n), zero-padded) ----
    #pragma unroll
    for (int kk = 0; kk < 7; ++kk) {
        const int k0 = kk * 8;
        float af[4];
        af[0] = sF[(k0 + t4    ) * PF + m0 + g    ];
        af[1] = sF[(k0 + t4    ) * PF + m0 + g + 8];
        af[2] = sF[(k0 + t4 + 4) * PF + m0 + g    ];
        af[3] = sF[(k0 + t4 + 4) * PF + m0 + g + 8];
        unsigned ah[4], al[4]; split4(af, ah, al);
        #pragma unroll
        for (int t = 0; t < 4; ++t) {
            const int j0 = n0 + 8 * t;
            float bf[2];
            bf[0] = sF[(k0 + t4    ) * PF + j0 + g];
            bf[1] = sF[(k0 + t4 + 4) * PF + j0 + g];
            unsigned bh[2], bl[2]; split2(bf, bh, bl);
            mma_split(accG[t], ah, al, bh, bl);
        }
    }

    // ---- Phase A2: H = F @ K_w  and  QF = F @ Q_w^T  (M=64(n), N=64(e), K=64(d)) ----
    #pragma unroll
    for (int kk = 0; kk < 8; ++kk) {
        const int k0 = kk * 8;
        float af[4];
        af[0] = sF[(m0 + g    ) * PF + k0 + t4    ];
        af[1] = sF[(m0 + g + 8) * PF + k0 + t4    ];
        af[2] = sF[(m0 + g    ) * PF + k0 + t4 + 4];
        af[3] = sF[(m0 + g + 8) * PF + k0 + t4 + 4];
        unsigned ah[4], al[4]; split4(af, ah, al);
        #pragma unroll
        for (int t = 0; t < 4; ++t) {
            const int j0 = n0 + 8 * t;
            // B_K[k][j] = K_w[k][j]  (row-major, type1 read)
            float bfk[2], bfq[2];
            bfk[0] = sK[(k0 + t4    ) * PK + j0 + g];
            bfk[1] = sK[(k0 + t4 + 4) * PK + j0 + g];
            // B_Q[k][j] = Q_w[j][k]  (transposed, type2 read)
            bfq[0] = sQ[(j0 + g) * PQ + k0 + t4    ];
            bfq[1] = sQ[(j0 + g) * PQ + k0 + t4 + 4];
            unsigned bh[2], bl[2];
            split2(bfk, bh, bl);
            mma_split(accH[t], ah, al, bh, bl);
            split2(bfq, bh, bl);
            mma_split(accQ[t], ah, al, bh, bl);
        }
    }

    // ---- store G, H fragments to smem ----
    #pragma unroll
    for (int t = 0; t < 4; ++t) {
        const int col = n0 + 8 * t + 2 * t4;
        *(float2*)&sG[(m0 + g    ) * PG + col] = make_float2(accG[t][0], accG[t][1]);
        *(float2*)&sG[(m0 + g + 8) * PG + col] = make_float2(accG[t][2], accG[t][3]);
        *(float2*)&sH[(m0 + g    ) * PH + col] = make_float2(accH[t][0], accH[t][1]);
        *(float2*)&sH[(m0 + g + 8) * PH + col] = make_float2(accH[t][2], accH[t][3]);
    }
    __syncthreads();

    // ---- Phase B: T = H @ G  (M=64(n), N=64(d), K=64(e)) ----
    float accT[4][4] = {};
    #pragma unroll
    for (int kk = 0; kk < 8; ++kk) {
        const int k0 = kk * 8;
        float af[4];
        af[0] = sH[(m0 + g    ) * PH + k0 + t4    ];
        af[1] = sH[(m0 + g + 8) * PH + k0 + t4    ];
        af[2] = sH[(m0 + g    ) * PH + k0 + t4 + 4];
        af[3] = sH[(m0 + g + 8) * PH + k0 + t4 + 4];
        unsigned ah[4], al[4]; split4(af, ah, al);
        #pragma unroll
        for (int t = 0; t < 4; ++t) {
            const int j0 = n0 + 8 * t;
            float bf[2];
            bf[0] = sG[(k0 + t4    ) * PG + j0 + g];
            bf[1] = sG[(k0 + t4 + 4) * PG + j0 + g];
            unsigned bh[2], bl[2]; split2(bf, bh, bl);
            mma_split(accT[t], ah, al, bh, bl);
        }
    }

    // ---- Epilogue: out = F .* T + QF  (rows < 50 only) ----
    float* ob = outg + (size_t)b * BTOK;
    const int r1 = m0 + g;
    const int r2 = m0 + g + 8;
    #pragma unroll
    for (int t = 0; t < 4; ++t) {
        const int col = n0 + 8 * t + 2 * t4;
        if (r1 < NTOK) {
            float2 f = *(const float2*)&sF[r1 * PF + col];
            float2 o;
            o.x = f.x * accT[t][0] + accQ[t][0];
            o.y = f.y * accT[t][1] + accQ[t][1];
            *(float2*)&ob[r1 * 64 + col] = o;
        }
        if (r2 < NTOK) {
            float2 f = *(const float2*)&sF[r2 * PF + col];
            float2 o;
            o.x = f.x * accT[t][2] + accQ[t][2];
            o.y = f.y * accT[t][3] + accQ[t][3];
            *(float2*)&ob[r2 * 64 + col] = o;
        }
    }
}

extern "C" void kernel_launch(void* const* d_in, const int* in_sizes, int n_in,
                              void* d_out, int out_size)
{
    const float* F  = (const float*)d_in[0];
    const float* Kw = (const float*)d_in[1];
    const float* Qw = (const float*)d_in[2];
    float* out      = (float*)d_out;

    const int B = in_sizes[0] / BTOK;                       // 8192
    const int smem_bytes = SMEM_FLOATS * sizeof(float);     // 90,112 B

    cudaFuncSetAttribute(SAM3E_kernel,
                         cudaFuncAttributeMaxDynamicSharedMemorySize, smem_bytes);

    SAM3E_kernel<<<B, 256, smem_bytes>>>(F, Kw, Qw, out);
}

// round 6
// speedup vs baseline: 1.1701x; 1.0073x over previous
#include <cuda_runtime.h>

#define NTOK 50
#define BTOK 3200      // 50*64
#define PF 72          // type1 reads conflict-free (8*t4+g perm); type2 A-reads 2-way (accepted)
#define PK 72          // K_w row-major [d][e], type1 reads conflict-free
#define PQ 68          // Q_w [e][d], type2 reads conflict-free (4*g+t4 perm)
#define PG 72          // aliases K region (same pitch)
#define PH 68          // aliases Q region (same pitch)

#define WORDS_F (64*PF)
#define WORDS_K (64*PK)
#define WORDS_Q (64*PQ)
#define SMEM_WORDS (2*WORDS_F + 2*WORDS_K + 2*WORDS_Q)   // 27136 words = 108,544 B

__device__ __forceinline__ float tf32f(float x) {
    unsigned u; asm("cvt.rna.tf32.f32 %0, %1;" : "=r"(u) : "f"(x));
    return __uint_as_float(u);
}

__device__ __forceinline__ void mma8(float* d, const unsigned* a, const unsigned* b) {
    asm volatile(
        "mma.sync.aligned.m16n8k8.row.col.f32.tf32.tf32.f32 "
        "{%0,%1,%2,%3}, {%4,%5,%6,%7}, {%8,%9}, {%0,%1,%2,%3};\n"
        : "+f"(d[0]), "+f"(d[1]), "+f"(d[2]), "+f"(d[3])
        : "r"(a[0]), "r"(a[1]), "r"(a[2]), "r"(a[3]), "r"(b[0]), "r"(b[1]));
}

// 3xTF32: acc += Ah*Bh + Al*Bh + Ah*Bl
__device__ __forceinline__ void mma_split(float* acc, const unsigned* ah, const unsigned* al,
                                          const unsigned* bh, const unsigned* bl) {
    mma8(acc, ah, bh);
    mma8(acc, al, bh);
    mma8(acc, ah, bl);
}

#define U(x) __float_as_uint(x)

__global__ __launch_bounds__(256, 2)
void SAM3E_kernel(const float* __restrict__ Fg,
                  const float* __restrict__ Kw,
                  const float* __restrict__ Qw,
                  float* __restrict__ outg)
{
    extern __shared__ float sm[];
    float* sFhi = sm;                          // [64][PF], rows 50..63 zero
    float* sFlo = sFhi + WORDS_F;
    float* sKhi = sFlo + WORDS_F;              // [64][PK]  (K_w as-is)   } aliased by G hi/lo
    float* sKlo = sKhi + WORDS_K;              //                          }
    float* sQhi = sKlo + WORDS_K;              // [64][PQ]  (Q_w as-is)   } aliased by H hi/lo
    float* sQlo = sQhi + WORDS_Q;              //                          }
    float* sGhi = sKhi;                        // G = F^T F (pitch PG=PK)
    float* sGlo = sKlo;
    float* sHhi = sQhi;                        // H = F @ K_w (pitch PH=PQ)
    float* sHlo = sQlo;

    const int b   = blockIdx.x;
    const int tid = threadIdx.x;
    const float* Fb = Fg + (size_t)b * BTOK;

    // ---- stage + split once ----
    for (int idx = tid; idx < BTOK; idx += 256) {
        int n = idx >> 6, d = idx & 63;
        float v = Fb[idx];
        float h = tf32f(v);
        sFhi[n * PF + d] = h;
        sFlo[n * PF + d] = tf32f(v - h);
    }
    for (int idx = tid; idx < 14 * PF; idx += 256) {     // zero pad rows 50..63
        sFhi[50 * PF + idx] = 0.0f;
        sFlo[50 * PF + idx] = 0.0f;
    }
    for (int idx = tid; idx < 4096; idx += 256) {
        int r = idx >> 6, c = idx & 63;
        float kv = Kw[idx];
        float kh = tf32f(kv);
        sKhi[r * PK + c] = kh;
        sKlo[r * PK + c] = tf32f(kv - kh);
        float qv = Qw[idx];
        float qh = tf32f(qv);
        sQhi[r * PQ + c] = qh;
        sQlo[r * PQ + c] = tf32f(qv - qh);
    }
    __syncthreads();

    const int w    = tid >> 5;
    const int lane = tid & 31;
    const int g    = lane >> 2;        // 0..7
    const int t4   = lane & 3;         // 0..3
    const int m0   = (w >> 1) * 16;    // m-band
    const int n0   = (w & 1) * 32;     // n-half (4 n8-tiles)

    float accG[4][4] = {};
    float accH[4][4] = {};
    float accQ[4][4] = {};

    // ---- Phase A1: G = F^T F   (M=64(d), N=64(d'), K=56(n) zero-padded) ----
    #pragma unroll
    for (int kk = 0; kk < 7; ++kk) {
        const int k0 = kk * 8;
        unsigned ah[4], al[4];
        ah[0] = U(sFhi[(k0 + t4    ) * PF + m0 + g    ]);
        ah[1] = U(sFhi[(k0 + t4    ) * PF + m0 + g + 8]);
        ah[2] = U(sFhi[(k0 + t4 + 4) * PF + m0 + g    ]);
        ah[3] = U(sFhi[(k0 + t4 + 4) * PF + m0 + g + 8]);
        al[0] = U(sFlo[(k0 + t4    ) * PF + m0 + g    ]);
        al[1] = U(sFlo[(k0 + t4    ) * PF + m0 + g + 8]);
        al[2] = U(sFlo[(k0 + t4 + 4) * PF + m0 + g    ]);
        al[3] = U(sFlo[(k0 + t4 + 4) * PF + m0 + g + 8]);
        #pragma unroll
        for (int t = 0; t < 4; ++t) {
            const int j0 = n0 + 8 * t;
            unsigned bh[2], bl[2];
            bh[0] = U(sFhi[(k0 + t4    ) * PF + j0 + g]);
            bh[1] = U(sFhi[(k0 + t4 + 4) * PF + j0 + g]);
            bl[0] = U(sFlo[(k0 + t4    ) * PF + j0 + g]);
            bl[1] = U(sFlo[(k0 + t4 + 4) * PF + j0 + g]);
            mma_split(accG[t], ah, al, bh, bl);
        }
    }

    // ---- Phase A2: H = F @ K_w and QF = F @ Q_w^T  (M=64(n), N=64(e), K=64(d)) ----
    #pragma unroll
    for (int kk = 0; kk < 8; ++kk) {
        const int k0 = kk * 8;
        unsigned ah[4], al[4];
        ah[0] = U(sFhi[(m0 + g    ) * PF + k0 + t4    ]);
        ah[1] = U(sFhi[(m0 + g + 8) * PF + k0 + t4    ]);
        ah[2] = U(sFhi[(m0 + g    ) * PF + k0 + t4 + 4]);
        ah[3] = U(sFhi[(m0 + g + 8) * PF + k0 + t4 + 4]);
        al[0] = U(sFlo[(m0 + g    ) * PF + k0 + t4    ]);
        al[1] = U(sFlo[(m0 + g + 8) * PF + k0 + t4    ]);
        al[2] = U(sFlo[(m0 + g    ) * PF + k0 + t4 + 4]);
        al[3] = U(sFlo[(m0 + g + 8) * PF + k0 + t4 + 4]);
        #pragma unroll
        for (int t = 0; t < 4; ++t) {
            const int j0 = n0 + 8 * t;
            unsigned bh[2], bl[2];
            // B_K[k][j] = K_w[k][j]  (type1 read)
            bh[0] = U(sKhi[(k0 + t4    ) * PK + j0 + g]);
            bh[1] = U(sKhi[(k0 + t4 + 4) * PK + j0 + g]);
            bl[0] = U(sKlo[(k0 + t4    ) * PK + j0 + g]);
            bl[1] = U(sKlo[(k0 + t4 + 4) * PK + j0 + g]);
            mma_split(accH[t], ah, al, bh, bl);
            // B_Q[k][j] = Q_w[j][k]  (type2 read)
            bh[0] = U(sQhi[(j0 + g) * PQ + k0 + t4    ]);
            bh[1] = U(sQhi[(j0 + g) * PQ + k0 + t4 + 4]);
            bl[0] = U(sQlo[(j0 + g) * PQ + k0 + t4    ]);
            bl[1] = U(sQlo[(j0 + g) * PQ + k0 + t4 + 4]);
            mma_split(accQ[t], ah, al, bh, bl);
        }
    }

    __syncthreads();   // all warps done reading sK/sQ -> safe to overwrite with G/H

    // ---- store G, H fragments (pre-split hi/lo) into aliased regions ----
    #pragma unroll
    for (int t = 0; t < 4; ++t) {
        const int col = n0 + 8 * t + 2 * t4;
        #pragma unroll
        for (int half = 0; half < 2; ++half) {
            const int row = m0 + g + 8 * half;
            float g0 = accG[t][2 * half], g1 = accG[t][2 * half + 1];
            float h0 = accH[t][2 * half], h1 = accH[t][2 * half + 1];
            float g0h = tf32f(g0), g1h = tf32f(g1);
            float h0h = tf32f(h0), h1h = tf32f(h1);
            *(float2*)&sGhi[row * PG + col] = make_float2(g0h, g1h);
            *(float2*)&sGlo[row * PG + col] = make_float2(tf32f(g0 - g0h), tf32f(g1 - g1h));
            *(float2*)&sHhi[row * PH + col] = make_float2(h0h, h1h);
            *(float2*)&sHlo[row * PH + col] = make_float2(tf32f(h0 - h0h), tf32f(h1 - h1h));
        }
    }
    __syncthreads();

    // ---- Phase B: T = H @ G  (M=64(n), N=64(d), K=64(e)) ----
    float accT[4][4] = {};
    #pragma unroll
    for (int kk = 0; kk < 8; ++kk) {
        const int k0 = kk * 8;
        unsigned ah[4], al[4];
        ah[0] = U(sHhi[(m0 + g    ) * PH + k0 + t4    ]);
        ah[1] = U(sHhi[(m0 + g + 8) * PH + k0 + t4    ]);
        ah[2] = U(sHhi[(m0 + g    ) * PH + k0 + t4 + 4]);
        ah[3] = U(sHhi[(m0 + g + 8) * PH + k0 + t4 + 4]);
        al[0] = U(sHlo[(m0 + g    ) * PH + k0 + t4    ]);
        al[1] = U(sHlo[(m0 + g + 8) * PH + k0 + t4    ]);
        al[2] = U(sHlo[(m0 + g    ) * PH + k0 + t4 + 4]);
        al[3] = U(sHlo[(m0 + g + 8) * PH + k0 + t4 + 4]);
        #pragma unroll
        for (int t = 0; t < 4; ++t) {
            const int j0 = n0 + 8 * t;
            unsigned bh[2], bl[2];
            bh[0] = U(sGhi[(k0 + t4    ) * PG + j0 + g]);
            bh[1] = U(sGhi[(k0 + t4 + 4) * PG + j0 + g]);
            bl[0] = U(sGlo[(k0 + t4    ) * PG + j0 + g]);
            bl[1] = U(sGlo[(k0 + t4 + 4) * PG + j0 + g]);
            mma_split(accT[t], ah, al, bh, bl);
        }
    }

    // ---- Epilogue: out = F .* T + QF  (rows < 50 only; F = hi + lo) ----
    float* ob = outg + (size_t)b * BTOK;
    const int r1 = m0 + g;
    const int r2 = m0 + g + 8;
    #pragma unroll
    for (int t = 0; t < 4; ++t) {
        const int col = n0 + 8 * t + 2 * t4;
        if (r1 < NTOK) {
            float2 fh = *(const float2*)&sFhi[r1 * PF + col];
            float2 fl = *(const float2*)&sFlo[r1 * PF + col];
            float2 o;
            o.x = (fh.x + fl.x) * accT[t][0] + accQ[t][0];
            o.y = (fh.y + fl.y) * accT[t][1] + accQ[t][1];
            *(float2*)&ob[r1 * 64 + col] = o;
        }
        if (r2 < NTOK) {
            float2 fh = *(const float2*)&sFhi[r2 * PF + col];
            float2 fl = *(const float2*)&sFlo[r2 * PF + col];
            float2 o;
            o.x = (fh.x + fl.x) * accT[t][2] + accQ[t][2];
            o.y = (fh.y + fl.y) * accT[t][3] + accQ[t][3];
            *(float2*)&ob[r2 * 64 + col] = o;
        }
    }
}

extern "C" void kernel_launch(void* const* d_in, const int* in_sizes, int n_in,
                              void* d_out, int out_size)
{
    const float* F  = (const float*)d_in[0];
    const float* Kw = (const float*)d_in[1];
    const float* Qw = (const float*)d_in[2];
    float* out      = (float*)d_out;

    const int B = in_sizes[0] / BTOK;                       // 8192
    const int smem_bytes = SMEM_WORDS * sizeof(float);      // 108,544 B

    cudaFuncSetAttribute(SAM3E_kernel,
                         cudaFuncAttributeMaxDynamicSharedMemorySize, smem_bytes);

    SAM3E_kernel<<<B, 256, smem_bytes>>>(F, Kw, Qw, out);
}